// round 4
// baseline (speedup 1.0000x reference)
#include <cuda_runtime.h>
#include <math.h>

#define Bb 64
#define Nn 1024
#define Hh 64
#define Tt 10
#define NBLK 148

#define NUNITS_E 1088
#define NUNITS_G 640
#define NUNITS_C 256
#define NUNITS_L 640
#define NUNITS_R 64
#define NUNITS_H 1024

// ---------------- scratch (device globals) ------------------------------------
__device__ __align__(16) float g_emb[Bb*Nn*Hh];
__device__ __align__(16) float g_h1 [Bb*Nn*Hh];
__device__ __align__(16) float g_h2 [Bb*Nn*Hh];
__device__ __align__(16) float g_G  [Bb*Tt*Hh*Hh];
__device__ __align__(16) float g_M  [Bb*Tt*Hh*Hh];
__device__ __align__(16) float g_inv[Bb*Nn];
__device__ int   g_idx[Bb*Tt*Nn];
__device__ int   g_cnt[Bb*Tt];
__device__ __align__(16) float g_ctx[Bb*Hh];
__device__ __align__(16) float g_hs [Bb*Hh];
__device__ int      g_bar_count = 0;
__device__ unsigned g_bar_gen   = 0;
__device__ int      g_ticket    = 0;

#define FMA4(A, s, v) { (A).x += (s)*(v).x; (A).y += (s)*(v).y; (A).z += (s)*(v).z; (A).w += (s)*(v).w; }
#define SUBBAR() asm volatile("bar.sync %0, 256;" :: "r"(sub + 1) : "memory")
#define NEXT_UNIT(u) { if (t2 == 0) s_unit[sub] = atomicAdd(&g_ticket, 1); \
                       SUBBAR(); u = s_unit[sub]; SUBBAR(); }

// grid-wide barrier: all NBLK blocks resident (grid==148 <= SM count) so
// spin-wait cannot deadlock. Last arriver resets the work ticket, then bumps
// the generation. __threadfence (gpu scope -> CCTL.IVALL) before arrival
// publishes writes; after release it invalidates L1 so rewritten global
// buffers (g_G, g_M) are re-fetched from L2.
__device__ __forceinline__ void grid_bar(unsigned& gen) {
    __threadfence();
    __syncthreads();
    if (threadIdx.x == 0) {
        if (atomicAdd(&g_bar_count, 1) == NBLK - 1) {
            g_ticket = 0;
            g_bar_count = 0;
            __threadfence();
            atomicExch(&g_bar_gen, gen + 1);
        } else {
            while (atomicAdd(&g_bar_gen, 0u) != gen + 1) __nanosleep(64);
        }
    }
    __syncthreads();
    __threadfence();
    gen += 1;
}

__global__ __launch_bounds__(512, 1) void mega(
    const float* __restrict__ tf,   const int* __restrict__ types,
    const float* __restrict__ prev,
    const float* __restrict__ ew1,  const float* __restrict__ eb1,
    const float* __restrict__ ew2,  const float* __restrict__ eb2,
    const float* __restrict__ cont,
    const float* __restrict__ gw,   const float* __restrict__ gb,
    const float* __restrict__ wih,  const float* __restrict__ whh,
    const float* __restrict__ bih,  const float* __restrict__ bhh,
    const float* __restrict__ hw1,  const float* __restrict__ hb1,
    const float* __restrict__ hw2,  const float* __restrict__ hb2,
    float* __restrict__ out)
{
    extern __shared__ __align__(16) float sm[];
    __shared__ int      s_idx[2][64];
    __shared__ float    s_inv[2][64];
    __shared__ int      s_cnt[2][16];
    __shared__ int      s_unit[2];
    __shared__ unsigned s_gen0;
    __shared__ __align__(16) float s_bias[64];
    __shared__ __align__(16) float s_gru[2][320];

    const int tid = threadIdx.x;
    const int sub = tid >> 8;          // 0 or 1: two independent 256-thread tiles
    const int t2  = tid & 255;
    const int tx  = t2 & 15, ty = t2 >> 4;

    // dyn smem: shared [0,4800) ; per-sub: A,B,C of 4352 floats each
    float* SW = sm;
    float* SA = sm + 4800 + sub*13056;
    float* SB = SA + 4352;
    float* SC = SB + 4352;

    if (tid == 0) s_gen0 = atomicAdd(&g_bar_gen, 0u);
    __syncthreads();
    unsigned gen = s_gen0;

    // ================= Phase E: encoder (1024 tiles) + bucket (64) =============
    for (int e = tid; e < 4096; e += 512) { int j = e >> 6, k = e & 63; SW[k*68 + j] = ew2[e]; }
    if (tid < 192) SW[4352 + tid] = ew1[tid];
    if (tid < 64)  { SW[4544 + tid] = eb1[tid]; SW[4608 + tid] = eb2[tid]; }
    __syncthreads();
    for (;;) {
        int u; NEXT_UNIT(u);
        if (u >= NUNITS_E) break;
        if (u < 1024) {
            int base = u << 6;
            if (t2 < 192) SB[t2] = tf[base*3 + t2];
            SUBBAR();
            #pragma unroll
            for (int it = 0; it < 16; ++it) {
                int e = t2 + it*256;
                int row = e >> 6, k = e & 63;
                float h = SB[row*3+0]*SW[4352+k*3+0] + SB[row*3+1]*SW[4352+k*3+1]
                        + SB[row*3+2]*SW[4352+k*3+2] + SW[4544+k];
                SA[row*68 + k] = fmaxf(h, 0.f);
            }
            SUBBAR();
            float4 acc[4];
            #pragma unroll
            for (int i = 0; i < 4; ++i) acc[i] = make_float4(0.f,0.f,0.f,0.f);
            #pragma unroll 8
            for (int kk = 0; kk < 64; ++kk) {
                float4 bb = *(const float4*)&SW[kk*68 + tx*4];
                float a0 = SA[(ty*4+0)*68 + kk];
                float a1 = SA[(ty*4+1)*68 + kk];
                float a2 = SA[(ty*4+2)*68 + kk];
                float a3 = SA[(ty*4+3)*68 + kk];
                FMA4(acc[0], a0, bb); FMA4(acc[1], a1, bb);
                FMA4(acc[2], a2, bb); FMA4(acc[3], a3, bb);
            }
            float4 bias = *(const float4*)&SW[4608 + tx*4];
            #pragma unroll
            for (int i = 0; i < 4; ++i) {
                acc[i].x += bias.x; acc[i].y += bias.y;
                acc[i].z += bias.z; acc[i].w += bias.w;
                float sq = acc[i].x*acc[i].x + acc[i].y*acc[i].y
                         + acc[i].z*acc[i].z + acc[i].w*acc[i].w;
                #pragma unroll
                for (int o = 8; o > 0; o >>= 1) sq += __shfl_xor_sync(0xffffffffu, sq, o);
                float inv = 1.f / fmaxf(sqrtf(sq), 1e-12f);
                int r = base + ty*4 + i;
                *(float4*)&g_emb[r*64 + tx*4] = acc[i];
                if (tx == 0) g_inv[r] = inv;
            }
        } else {
            int b = u - 1024;
            if (t2 < Tt) s_cnt[sub][t2] = 0;
            if (t2 < 64) g_ctx[b*64 + t2] = 0.f;
            SUBBAR();
            #pragma unroll
            for (int it = 0; it < 4; ++it) {
                int n = it*256 + t2;
                int t = types[b*1024 + n];
                int pos = atomicAdd(&s_cnt[sub][t], 1);
                g_idx[(b*Tt + t)*1024 + pos] = n;
            }
            SUBBAR();
            if (t2 < Tt) g_cnt[b*Tt + t2] = s_cnt[sub][t2];
        }
    }
    grid_bar(gen);

    // ================= layers ==================================================
    for (int l = 0; l < 2; ++l) {
        // ---- Phase G: G[b,t] = Nrm_rows^T @ H_rows ----
        {
            const float4* emb4 = (const float4*)g_emb;
            const float4* h4   = (l == 0) ? emb4 : (const float4*)g_h1;
            for (;;) {
                int u; NEXT_UNIT(u);
                if (u >= NUNITS_G) break;
                int b = u / 10, t = u - b*10;
                int Kt = g_cnt[b*Tt + t];
                const int* lst = &g_idx[(b*Tt + t)*1024];
                float4 acc[4];
                #pragma unroll
                for (int i = 0; i < 4; ++i) acc[i] = make_float4(0.f,0.f,0.f,0.f);
                for (int r0 = 0; r0 < Kt; r0 += 64) {
                    SUBBAR();
                    if (t2 < 64) {
                        int row = (r0 + t2 < Kt) ? lst[r0 + t2] : -1;
                        s_idx[sub][t2] = row;
                        s_inv[sub][t2] = (row >= 0) ? g_inv[(b << 10) + row] : 0.f;
                    }
                    SUBBAR();
                    #pragma unroll
                    for (int it = 0; it < 4; ++it) {
                        int e = t2 + it*256;
                        int rr = e >> 4, kq = e & 15;
                        int row = s_idx[sub][rr];
                        float4 v = make_float4(0.f,0.f,0.f,0.f);
                        float4 w = v;
                        if (row >= 0) {
                            int gi = ((b << 10) + row)*16 + kq;
                            v = emb4[gi];
                            w = (l == 0) ? v : h4[gi];
                        }
                        float iv = s_inv[sub][rr];
                        *(float4*)&SB[rr*68 + kq*4] = w;
                        v.x *= iv; v.y *= iv; v.z *= iv; v.w *= iv;
                        *(float4*)&SA[rr*68 + kq*4] = v;
                    }
                    SUBBAR();
                    #pragma unroll 8
                    for (int rr = 0; rr < 64; ++rr) {
                        float4 a  = *(const float4*)&SA[rr*68 + ty*4];
                        float4 bb = *(const float4*)&SB[rr*68 + tx*4];
                        FMA4(acc[0], a.x, bb); FMA4(acc[1], a.y, bb);
                        FMA4(acc[2], a.z, bb); FMA4(acc[3], a.w, bb);
                    }
                }
                float* Gp = &g_G[(b*Tt + t)*4096];
                #pragma unroll
                for (int i = 0; i < 4; ++i)
                    *(float4*)&Gp[(ty*4 + i)*64 + tx*4] = acc[i];
            }
        }
        grid_bar(gen);

        // ---- Phase C: M[b,tp] = sum_t sigmoid(C[tp,t]) G[b,t] ----
        {
            if (tid < Tt*Tt) SW[tid] = 1.f / (1.f + expf(-cont[tid]));
            __syncthreads();
            for (;;) {
                int u; NEXT_UNIT(u);
                if (u >= NUNITS_C) break;
                int b = u >> 2, seg = u & 3;
                int i4 = seg*256 + t2;
                const float4* G4 = (const float4*)g_G + (size_t)b*10240;
                float4*       M4 = (float4*)g_M       + (size_t)b*10240;
                float4 gg[Tt];
                #pragma unroll
                for (int t = 0; t < Tt; ++t) gg[t] = G4[t*1024 + i4];
                #pragma unroll
                for (int tp = 0; tp < Tt; ++tp) {
                    float4 o = make_float4(0.f,0.f,0.f,0.f);
                    #pragma unroll
                    for (int t = 0; t < Tt; ++t) { float s = SW[tp*Tt + t]; FMA4(o, s, gg[t]); }
                    M4[tp*1024 + i4] = o;
                }
            }
        }
        grid_bar(gen);

        // ---- Phase L: Agg = Nrm @ M ; Hout = relu((H+Agg)@W^T + b) ----
        {
            const float* hin  = (l == 0) ? g_emb : g_h1;
            float*       hout = (l == 0) ? g_h1  : g_h2;
            const float* Wp = gw + l*4096;
            for (int e = tid; e < 4096; e += 512) { int c = e >> 6, k = e & 63; SW[k*68 + c] = Wp[e]; }
            if (tid < 64) s_bias[tid] = gb[l*64 + tid];
            __syncthreads();
            const float4* emb4 = (const float4*)g_emb;
            for (;;) {
                int u; NEXT_UNIT(u);
                if (u >= NUNITS_L) break;
                int b = u / 10, t = u - b*10;
                int Kt = g_cnt[b*Tt + t];
                if (Kt == 0) continue;
                const float4* Mp4 = (const float4*)&g_M[(b*Tt + t)*4096];
                #pragma unroll
                for (int it = 0; it < 4; ++it) {
                    int e = t2 + it*256;
                    int rr = e >> 4, kq = e & 15;
                    *(float4*)&SA[rr*68 + kq*4] = Mp4[e];
                }
                const int* lst = &g_idx[(b*Tt + t)*1024];
                float4 psum = make_float4(0.f,0.f,0.f,0.f);
                for (int r0 = 0; r0 < Kt; r0 += 64) {
                    SUBBAR();
                    if (t2 < 64) {
                        int row = (r0 + t2 < Kt) ? lst[r0 + t2] : -1;
                        s_idx[sub][t2] = row;
                        s_inv[sub][t2] = (row >= 0) ? g_inv[(b << 10) + row] : 0.f;
                    }
                    SUBBAR();
                    #pragma unroll
                    for (int it = 0; it < 4; ++it) {
                        int e = t2 + it*256;
                        int rr = e >> 4, kq = e & 15;
                        int row = s_idx[sub][rr];
                        float4 v = make_float4(0.f,0.f,0.f,0.f);
                        if (row >= 0) v = emb4[((b << 10) + row)*16 + kq];
                        float iv = s_inv[sub][rr];
                        v.x *= iv; v.y *= iv; v.z *= iv; v.w *= iv;
                        *(float4*)&SB[rr*68 + kq*4] = v;
                    }
                    SUBBAR();
                    float4 acc[4];
                    #pragma unroll
                    for (int i = 0; i < 4; ++i) acc[i] = make_float4(0.f,0.f,0.f,0.f);
                    #pragma unroll 8
                    for (int kk = 0; kk < 64; ++kk) {
                        float4 bb = *(const float4*)&SA[kk*68 + tx*4];
                        float a0 = SB[(ty*4+0)*68 + kk];
                        float a1 = SB[(ty*4+1)*68 + kk];
                        float a2 = SB[(ty*4+2)*68 + kk];
                        float a3 = SB[(ty*4+3)*68 + kk];
                        FMA4(acc[0], a0, bb); FMA4(acc[1], a1, bb);
                        FMA4(acc[2], a2, bb); FMA4(acc[3], a3, bb);
                    }
                    #pragma unroll
                    for (int i = 0; i < 4; ++i) {
                        int row = s_idx[sub][ty*4 + i];
                        float4 x = acc[i];
                        if (row >= 0) {
                            float4 hv = *(const float4*)&hin[((b << 10) + row)*64 + tx*4];
                            x.x += hv.x; x.y += hv.y; x.z += hv.z; x.w += hv.w;
                        } else {
                            x = make_float4(0.f,0.f,0.f,0.f);
                        }
                        *(float4*)&SC[(ty*4+i)*68 + tx*4] = x;
                    }
                    SUBBAR();
                    float4 acc2[4];
                    #pragma unroll
                    for (int i = 0; i < 4; ++i) acc2[i] = make_float4(0.f,0.f,0.f,0.f);
                    #pragma unroll 8
                    for (int kk = 0; kk < 64; ++kk) {
                        float4 bb = *(const float4*)&SW[kk*68 + tx*4];
                        float a0 = SC[(ty*4+0)*68 + kk];
                        float a1 = SC[(ty*4+1)*68 + kk];
                        float a2 = SC[(ty*4+2)*68 + kk];
                        float a3 = SC[(ty*4+3)*68 + kk];
                        FMA4(acc2[0], a0, bb); FMA4(acc2[1], a1, bb);
                        FMA4(acc2[2], a2, bb); FMA4(acc2[3], a3, bb);
                    }
                    float4 bias = *(const float4*)&s_bias[tx*4];
                    #pragma unroll
                    for (int i = 0; i < 4; ++i) {
                        int row = s_idx[sub][ty*4 + i];
                        if (row >= 0) {
                            float4 o = acc2[i];
                            o.x = fmaxf(o.x + bias.x, 0.f);
                            o.y = fmaxf(o.y + bias.y, 0.f);
                            o.z = fmaxf(o.z + bias.z, 0.f);
                            o.w = fmaxf(o.w + bias.w, 0.f);
                            *(float4*)&hout[((b << 10) + row)*64 + tx*4] = o;
                            if (l == 1) { psum.x += o.x; psum.y += o.y; psum.z += o.z; psum.w += o.w; }
                        }
                    }
                }
                if (l == 1) {
                    SUBBAR();
                    *(float4*)&SB[ty*64 + tx*4] = psum;
                    SUBBAR();
                    if (t2 < 64) {
                        float s = 0.f;
                        #pragma unroll
                        for (int q = 0; q < 16; ++q) s += SB[q*64 + t2];
                        atomicAdd(&g_ctx[b*64 + t2], s);
                    }
                }
            }
        }
        grid_bar(gen);
    }

    // ================= Phase R: GRU + head-state precompute =====================
    for (;;) {
        int u; NEXT_UNIT(u);
        if (u >= NUNITS_R) break;
        int b = u;
        float* Gm = s_gru[sub];   // [0,64) ctx | [64,96) prev | [96,192) gi | [192,288) gh | [288,320) st
        if (t2 < 64) Gm[t2] = g_ctx[b*64 + t2] * (1.f/1024.f);
        if (t2 >= 64 && t2 < 96) Gm[t2] = prev[b*32 + (t2 - 64)];
        SUBBAR();
        if (t2 < 96) {
            float gi = bih[t2], gh = bhh[t2];
            #pragma unroll 16
            for (int k = 0; k < 64; ++k) gi += Gm[k] * wih[t2*64 + k];
            #pragma unroll 16
            for (int k = 0; k < 32; ++k) gh += Gm[64 + k] * whh[t2*32 + k];
            Gm[96 + t2] = gi; Gm[192 + t2] = gh;
        }
        SUBBAR();
        if (t2 < 32) {
            float r  = 1.f / (1.f + expf(-(Gm[96  + t2] + Gm[192 + t2])));
            float z  = 1.f / (1.f + expf(-(Gm[128 + t2] + Gm[224 + t2])));
            float nn = tanhf(Gm[160 + t2] + r * Gm[256 + t2]);
            float ns = (1.f - z)*nn + z*Gm[64 + t2];
            Gm[288 + t2] = ns;
            out[Bb*Nn + b*32 + t2] = ns;
        }
        SUBBAR();
        if (t2 < 64) {
            float v = hb1[t2];
            #pragma unroll
            for (int k = 0; k < 32; ++k) v += hw1[t2*96 + 64 + k] * Gm[288 + k];
            g_hs[b*64 + t2] = v;
        }
    }
    grid_bar(gen);

    // ================= Phase H: head (K reduced to 64) ==========================
    {
        for (int e = tid; e < 4096; e += 512) { int j = e >> 6, k = e & 63; SW[k*68 + j] = hw1[j*96 + k]; }
        if (tid < 64) SW[4352 + tid] = hw2[tid];
        __syncthreads();
        float b2v = hb2[0];
        const float4* h24 = (const float4*)g_h2;
        for (;;) {
            int u; NEXT_UNIT(u);
            if (u >= NUNITS_H) break;
            int base = u << 6;
            int b = u >> 4;
            #pragma unroll
            for (int it = 0; it < 4; ++it) {
                int e = t2 + it*256;
                int rr = e >> 4, kq = e & 15;
                *(float4*)&SA[rr*68 + kq*4] = h24[(base + rr)*16 + kq];
            }
            SUBBAR();
            float4 v4 = *(const float4*)&g_hs[b*64 + tx*4];
            float4 acc[4] = {v4, v4, v4, v4};
            #pragma unroll 8
            for (int kk = 0; kk < 64; ++kk) {
                float4 bb = *(const float4*)&SW[kk*68 + tx*4];
                float a0 = SA[(ty*4+0)*68 + kk];
                float a1 = SA[(ty*4+1)*68 + kk];
                float a2 = SA[(ty*4+2)*68 + kk];
                float a3 = SA[(ty*4+3)*68 + kk];
                FMA4(acc[0], a0, bb); FMA4(acc[1], a1, bb);
                FMA4(acc[2], a2, bb); FMA4(acc[3], a3, bb);
            }
            float4 w2v = *(const float4*)&SW[4352 + tx*4];
            #pragma unroll
            for (int i = 0; i < 4; ++i) {
                float y = fmaxf(acc[i].x, 0.f)*w2v.x + fmaxf(acc[i].y, 0.f)*w2v.y
                        + fmaxf(acc[i].z, 0.f)*w2v.z + fmaxf(acc[i].w, 0.f)*w2v.w;
                #pragma unroll
                for (int o = 8; o > 0; o >>= 1) y += __shfl_xor_sync(0xffffffffu, y, o);
                if (tx == 0) out[base + ty*4 + i] = y + b2v;
            }
        }
    }
    grid_bar(gen);   // also resets g_ticket for the next launch/replay
}

// ---------------- launch --------------------------------------------------------
extern "C" void kernel_launch(void* const* d_in, const int* in_sizes, int n_in,
                              void* d_out, int out_size)
{
    const float* tf    = (const float*)d_in[0];
    const int*   types = (const int*)  d_in[1];
    const float* prev  = (const float*)d_in[2];
    const float* ew1   = (const float*)d_in[3];
    const float* eb1   = (const float*)d_in[4];
    const float* ew2   = (const float*)d_in[5];
    const float* eb2   = (const float*)d_in[6];
    const float* cont  = (const float*)d_in[7];
    const float* gw    = (const float*)d_in[8];
    const float* gb    = (const float*)d_in[9];
    const float* wih   = (const float*)d_in[10];
    const float* whh   = (const float*)d_in[11];
    const float* bih   = (const float*)d_in[12];
    const float* bhh   = (const float*)d_in[13];
    const float* hw1   = (const float*)d_in[14];
    const float* hb1   = (const float*)d_in[15];
    const float* hw2   = (const float*)d_in[16];
    const float* hb2   = (const float*)d_in[17];
    float* out = (float*)d_out;

    cudaFuncSetAttribute(mega, cudaFuncAttributeMaxDynamicSharedMemorySize, 123648);
    mega<<<NBLK, 512, 123648>>>(tf, types, prev, ew1, eb1, ew2, eb2, cont,
                                gw, gb, wih, whh, bih, bhh, hw1, hb1, hw2, hb2, out);
}

// round 5
// speedup vs baseline: 1.1417x; 1.1417x over previous
#include <cuda_runtime.h>
#include <math.h>

#define Bb 64
#define Nn 1024
#define Hh 64
#define Tt 10

// ---------------- scratch (device globals) ------------------------------------
__device__ __align__(16) float g_emb[Bb*Nn*Hh];
__device__ __align__(16) float g_h1 [Bb*Nn*Hh];
__device__ __align__(16) float g_h2 [Bb*Nn*Hh];
__device__ __align__(16) float g_G  [Bb*Tt*Hh*Hh];
__device__ __align__(16) float g_inv[Bb*Nn];
__device__ int   g_idx[Bb*Tt*Nn];
__device__ int   g_cnt[Bb*Tt];
__device__ __align__(16) float g_ctx[Bb*Hh];

typedef unsigned long long ull;

#define FMA4(A, s, v) { (A).x += (s)*(v).x; (A).y += (s)*(v).y; (A).z += (s)*(v).z; (A).w += (s)*(v).w; }
#define FMA2(acc, a2, b2)  asm("fma.rn.f32x2 %0, %1, %2, %0;" : "+l"(acc) : "l"(a2), "l"(b2))
#define PACK_DUP(out, x)   asm("mov.b64 %0, {%1, %1};" : "=l"(out) : "r"(__float_as_uint(x)))
#define UNPACK2(lo, hi, p) asm("mov.b64 {%0, %1}, %2;" : "=r"(lo), "=r"(hi) : "l"(p))

__device__ __forceinline__ float4 acc_f4(ull p0, ull p1) {
    unsigned a, b, c, d;
    UNPACK2(a, b, p0); UNPACK2(c, d, p1);
    return make_float4(__uint_as_float(a), __uint_as_float(b),
                       __uint_as_float(c), __uint_as_float(d));
}

// 16 fp32 FMAs as 8 packed FFMA2: 4 row-scalars x one float4 of B
__device__ __forceinline__ void mk16(ull* acc, float a0, float a1, float a2, float a3,
                                     const float* bp) {
    ulonglong2 bv = *(const ulonglong2*)bp;
    ull ap;
    PACK_DUP(ap, a0); FMA2(acc[0], ap, bv.x); FMA2(acc[1], ap, bv.y);
    PACK_DUP(ap, a1); FMA2(acc[2], ap, bv.x); FMA2(acc[3], ap, bv.y);
    PACK_DUP(ap, a2); FMA2(acc[4], ap, bv.x); FMA2(acc[5], ap, bv.y);
    PACK_DUP(ap, a3); FMA2(acc[6], ap, bv.x); FMA2(acc[7], ap, bv.y);
}

// ---------------- K1: encoder (blocks 0..1023) + bucket (1024..1087) -----------
__global__ __launch_bounds__(256) void k_encbkt(
    const float* __restrict__ tf, const int* __restrict__ types,
    const float* __restrict__ w1, const float* __restrict__ b1,
    const float* __restrict__ w2, const float* __restrict__ b2)
{
    __shared__ __align__(16) float s_h1 [64*68];
    __shared__ __align__(16) float s_w2t[64*68];
    __shared__ __align__(16) float s_f[192];
    __shared__ __align__(16) float s_w1[192];
    __shared__ __align__(16) float s_b1[64];
    __shared__ __align__(16) float s_b2[64];
    __shared__ int s_cnt[16];
    int tid = threadIdx.x;

    if (blockIdx.x >= 1024) {               // ---- bucket path ----
        int b = blockIdx.x - 1024;
        if (tid < Tt) s_cnt[tid] = 0;
        if (tid < 64) g_ctx[b*64 + tid] = 0.f;
        __syncthreads();
        #pragma unroll
        for (int it = 0; it < 4; ++it) {
            int n = it*256 + tid;
            int t = types[b*Nn + n];
            int pos = atomicAdd(&s_cnt[t], 1);
            g_idx[(b*Tt + t)*Nn + pos] = n;
        }
        __syncthreads();
        if (tid < Tt) g_cnt[b*Tt + tid] = s_cnt[tid];
        return;
    }

    int tx = tid & 15, ty = tid >> 4;
    int base = blockIdx.x * 64;

    #pragma unroll
    for (int it = 0; it < 16; ++it) {
        int e = tid + it*256;
        int j = e >> 6, k = e & 63;
        s_w2t[k*68 + j] = w2[e];
    }
    if (tid < 192) { s_f[tid] = tf[base*3 + tid]; s_w1[tid] = w1[tid]; }
    if (tid < 64)  { s_b1[tid] = b1[tid]; s_b2[tid] = b2[tid]; }
    __syncthreads();

    #pragma unroll
    for (int it = 0; it < 16; ++it) {
        int e = tid + it*256;
        int row = e >> 6, k = e & 63;
        float h = s_f[row*3+0]*s_w1[k*3+0] + s_f[row*3+1]*s_w1[k*3+1]
                + s_f[row*3+2]*s_w1[k*3+2] + s_b1[k];
        s_h1[row*68 + k] = fmaxf(h, 0.f);
    }
    __syncthreads();

    ull acc[8] = {0,0,0,0,0,0,0,0};
    #pragma unroll 8
    for (int kk = 0; kk < 64; ++kk) {
        float a0 = s_h1[(ty*4+0)*68 + kk];
        float a1 = s_h1[(ty*4+1)*68 + kk];
        float a2 = s_h1[(ty*4+2)*68 + kk];
        float a3 = s_h1[(ty*4+3)*68 + kk];
        mk16(acc, a0, a1, a2, a3, &s_w2t[kk*68 + tx*4]);
    }
    float4 bias = *(const float4*)&s_b2[tx*4];
    #pragma unroll
    for (int i = 0; i < 4; ++i) {
        float4 v = acc_f4(acc[2*i], acc[2*i+1]);
        v.x += bias.x; v.y += bias.y; v.z += bias.z; v.w += bias.w;
        float sq = v.x*v.x + v.y*v.y + v.z*v.z + v.w*v.w;
        #pragma unroll
        for (int o = 8; o > 0; o >>= 1) sq += __shfl_xor_sync(0xffffffffu, sq, o);
        float inv = 1.f / fmaxf(sqrtf(sq), 1e-12f);
        int r = base + ty*4 + i;
        *(float4*)&g_emb[r*64 + tx*4] = v;
        if (tx == 0) g_inv[r] = inv;
    }
}

// ---------------- K2: G_t = Nrm^T @ H per (t,b) --------------------------------
__global__ __launch_bounds__(256) void k_gmat(int layer)
{
    const float4* emb4 = (const float4*)g_emb;
    const float4* h4   = (const float4*)((layer == 0) ? g_emb : g_h1);
    __shared__ __align__(16) float s_A [64*68];
    __shared__ __align__(16) float s_Bh[64*68];
    __shared__ int   s_idx[64];
    __shared__ float s_inv[64];
    int t = blockIdx.x, b = blockIdx.y;
    int tid = threadIdx.x;
    int tx = tid & 15, ty = tid >> 4;
    int Kt = g_cnt[b*Tt + t];
    const int* lst = &g_idx[(b*Tt + t)*Nn];
    ull acc[8] = {0,0,0,0,0,0,0,0};

    for (int r0 = 0; r0 < Kt; r0 += 64) {
        __syncthreads();
        if (tid < 64) {
            int row = (r0 + tid < Kt) ? lst[r0 + tid] : -1;
            s_idx[tid] = row;
            s_inv[tid] = (row >= 0) ? g_inv[(b<<10) + row] : 0.f;
        }
        __syncthreads();
        #pragma unroll
        for (int it = 0; it < 4; ++it) {
            int e = tid + it*256;
            int rr = e >> 4, kq = e & 15;
            int row = s_idx[rr];
            float4 v = make_float4(0.f,0.f,0.f,0.f);
            float4 w = v;
            if (row >= 0) {
                int gi = ((b<<10) + row)*16 + kq;
                v = emb4[gi];
                w = (layer == 0) ? v : h4[gi];
            }
            float iv = s_inv[rr];
            *(float4*)&s_Bh[rr*68 + kq*4] = w;
            v.x *= iv; v.y *= iv; v.z *= iv; v.w *= iv;
            *(float4*)&s_A[rr*68 + kq*4] = v;
        }
        __syncthreads();
        #pragma unroll 8
        for (int rr = 0; rr < 64; ++rr) {
            float4 a = *(const float4*)&s_A[rr*68 + ty*4];
            mk16(acc, a.x, a.y, a.z, a.w, &s_Bh[rr*68 + tx*4]);
        }
    }
    float* Gp = &g_G[(b*Tt + t)*4096];
    #pragma unroll
    for (int i = 0; i < 4; ++i)
        *(float4*)&Gp[(ty*4 + i)*64 + tx*4] = acc_f4(acc[2*i], acc[2*i+1]);
}

// ---------------- K3: inline M + Agg = Nrm @ M ; Hout = relu((H+Agg)@W^T+b) ----
// grid (10,64), 256 threads, dyn smem 69632
__global__ __launch_bounds__(256) void k_layer(
    int layer, const float* __restrict__ cont,
    const float* __restrict__ gnn_w, const float* __restrict__ gnn_b)
{
    const float* hin  = (layer == 0) ? g_emb : g_h1;
    float*       hout = (layer == 0) ? g_h1  : g_h2;
    const float4* emb4 = (const float4*)g_emb;
    extern __shared__ __align__(16) float sm[];
    float* SA = sm;            // M   [k][d] stride 68
    float* SW = sm + 4352;     // W^T [k][c] stride 68
    float* SB = sm + 8704;     // gathered nrm [r][k] stride 68
    float* SC = sm + 13056;    // X   [r][k] stride 68
    __shared__ int   s_idx[64];
    __shared__ float s_inv[64];
    __shared__ __align__(16) float s_bias[64];
    __shared__ float s_sg[16];
    __shared__ __align__(16) float s_csum[16][64];

    int t = blockIdx.x, b = blockIdx.y;
    int tid = threadIdx.x;
    int tx = tid & 15, ty = tid >> 4;
    int Kt = g_cnt[b*Tt + t];
    if (Kt == 0) return;

    const float* Wp = gnn_w + layer*4096;
    if (tid < Tt)  s_sg[tid] = 1.f / (1.f + expf(-cont[t*Tt + tid]));
    if (tid < 64)  s_bias[tid] = gnn_b[layer*64 + tid];
    #pragma unroll
    for (int it = 0; it < 16; ++it) {
        int e = tid + it*256;
        SW[(e & 63)*68 + (e >> 6)] = Wp[e];     // transpose -> [k][c]
    }
    __syncthreads();

    // Build M[b,t] = sum_tp sigmoid(C[t,tp]) * G[b,tp] directly into SA
    const float4* Gb = (const float4*)&g_G[b*Tt*4096];
    #pragma unroll
    for (int it = 0; it < 4; ++it) {
        int e = tid + it*256;                    // float4 index 0..1023
        float4 m = make_float4(0.f,0.f,0.f,0.f);
        #pragma unroll
        for (int tp = 0; tp < Tt; ++tp) {
            float s = s_sg[tp];
            float4 gv = Gb[tp*1024 + e];
            FMA4(m, s, gv);
        }
        *(float4*)&SA[(e >> 4)*68 + (e & 15)*4] = m;
    }

    const int* lst = &g_idx[(b*Tt + t)*Nn];
    float4 psum = make_float4(0.f,0.f,0.f,0.f);

    for (int r0 = 0; r0 < Kt; r0 += 64) {
        __syncthreads();
        if (tid < 64) {
            int row = (r0 + tid < Kt) ? lst[r0 + tid] : -1;
            s_idx[tid] = row;
            s_inv[tid] = (row >= 0) ? g_inv[(b<<10) + row] : 0.f;
        }
        __syncthreads();
        #pragma unroll
        for (int it = 0; it < 4; ++it) {
            int e = tid + it*256;
            int rr = e >> 4, kq = e & 15;
            int row = s_idx[rr];
            float4 v = make_float4(0.f,0.f,0.f,0.f);
            if (row >= 0) v = emb4[((b<<10) + row)*16 + kq];
            float iv = s_inv[rr];
            v.x *= iv; v.y *= iv; v.z *= iv; v.w *= iv;
            *(float4*)&SB[rr*68 + kq*4] = v;
        }
        __syncthreads();

        // GEMM1: Agg = nrm @ M
        ull acc[8] = {0,0,0,0,0,0,0,0};
        #pragma unroll 8
        for (int kk = 0; kk < 64; ++kk) {
            float a0 = SB[(ty*4+0)*68 + kk];
            float a1 = SB[(ty*4+1)*68 + kk];
            float a2 = SB[(ty*4+2)*68 + kk];
            float a3 = SB[(ty*4+3)*68 + kk];
            mk16(acc, a0, a1, a2, a3, &SA[kk*68 + tx*4]);
        }
        #pragma unroll
        for (int i = 0; i < 4; ++i) {
            int row = s_idx[ty*4 + i];
            float4 x = acc_f4(acc[2*i], acc[2*i+1]);
            if (row >= 0) {
                float4 hv = *(const float4*)&hin[((b<<10) + row)*64 + tx*4];
                x.x += hv.x; x.y += hv.y; x.z += hv.z; x.w += hv.w;
            } else {
                x = make_float4(0.f,0.f,0.f,0.f);
            }
            *(float4*)&SC[(ty*4+i)*68 + tx*4] = x;
        }
        __syncthreads();

        // GEMM2: Out = X @ W^T
        ull acc2[8] = {0,0,0,0,0,0,0,0};
        #pragma unroll 8
        for (int kk = 0; kk < 64; ++kk) {
            float a0 = SC[(ty*4+0)*68 + kk];
            float a1 = SC[(ty*4+1)*68 + kk];
            float a2 = SC[(ty*4+2)*68 + kk];
            float a3 = SC[(ty*4+3)*68 + kk];
            mk16(acc2, a0, a1, a2, a3, &SW[kk*68 + tx*4]);
        }
        float4 bias = *(const float4*)&s_bias[tx*4];
        #pragma unroll
        for (int i = 0; i < 4; ++i) {
            int row = s_idx[ty*4 + i];
            if (row >= 0) {
                float4 o = acc_f4(acc2[2*i], acc2[2*i+1]);
                o.x = fmaxf(o.x + bias.x, 0.f);
                o.y = fmaxf(o.y + bias.y, 0.f);
                o.z = fmaxf(o.z + bias.z, 0.f);
                o.w = fmaxf(o.w + bias.w, 0.f);
                *(float4*)&hout[((b<<10) + row)*64 + tx*4] = o;
                if (layer == 1) { psum.x += o.x; psum.y += o.y; psum.z += o.z; psum.w += o.w; }
            }
        }
    }

    if (layer == 1) {
        __syncthreads();
        *(float4*)&s_csum[ty][tx*4] = psum;
        __syncthreads();
        if (tid < 64) {
            float s = 0.f;
            #pragma unroll
            for (int q = 0; q < 16; ++q) s += s_csum[q][tid];
            atomicAdd(&g_ctx[b*64 + tid], s);
        }
    }
}

// ---------------- K4: head (+GRU computed per-block, K reduced to 64) ----------
// grid 1024, 256 threads, static smem
__global__ __launch_bounds__(256) void k_head(
    const float* __restrict__ prev, const float* __restrict__ wih,
    const float* __restrict__ whh,  const float* __restrict__ bih,
    const float* __restrict__ bhh,
    const float* __restrict__ w1, const float* __restrict__ b1,
    const float* __restrict__ w2, const float* __restrict__ b2,
    float* __restrict__ out)
{
    __shared__ __align__(16) float s_X[64*68];
    __shared__ __align__(16) float s_W[64*68];
    __shared__ __align__(16) float s_g[320];   // ctx|prev|gi|gh|ns
    __shared__ __align__(16) float s_hs[64];
    __shared__ __align__(16) float s_w2[64];
    int tid = threadIdx.x;
    int tx = tid & 15, ty = tid >> 4;
    int u = blockIdx.x;
    int base = u << 6;
    int b = u >> 4;

    // stage GRU inputs + weights + rows
    if (tid < 64)  s_g[tid] = g_ctx[b*64 + tid] * (1.f/1024.f);
    else if (tid < 96) s_g[tid] = prev[b*32 + (tid - 64)];
    #pragma unroll
    for (int it = 0; it < 16; ++it) {
        int e = tid + it*256;
        int j = e >> 6, k = e & 63;
        s_W[k*68 + j] = w1[j*96 + k];           // W1[:, :64] transposed
    }
    if (tid < 64) s_w2[tid] = w2[tid];
    const float4* h24 = (const float4*)g_h2;
    #pragma unroll
    for (int it = 0; it < 4; ++it) {
        int e = tid + it*256;
        int rr = e >> 4, kq = e & 15;
        *(float4*)&s_X[rr*68 + kq*4] = h24[(base + rr)*16 + kq];
    }
    __syncthreads();

    // GRU (redundant per block; block u%16==0 writes the state output)
    if (tid < 96) {
        float gi = bih[tid], gh = bhh[tid];
        #pragma unroll 16
        for (int k = 0; k < 64; ++k) gi += s_g[k] * wih[tid*64 + k];
        #pragma unroll 16
        for (int k = 0; k < 32; ++k) gh += s_g[64 + k] * whh[tid*32 + k];
        s_g[96 + tid] = gi; s_g[192 + tid] = gh;
    }
    __syncthreads();
    if (tid < 32) {
        float r  = 1.f / (1.f + expf(-(s_g[96  + tid] + s_g[192 + tid])));
        float z  = 1.f / (1.f + expf(-(s_g[128 + tid] + s_g[224 + tid])));
        float nn = tanhf(s_g[160 + tid] + r * s_g[256 + tid]);
        float ns = (1.f - z)*nn + z*s_g[64 + tid];
        s_g[288 + tid] = ns;
        if ((u & 15) == 0) out[Bb*Nn + b*32 + tid] = ns;
    }
    __syncthreads();
    if (tid < 64) {
        float v = b1[tid];
        #pragma unroll
        for (int k = 0; k < 32; ++k) v += w1[tid*96 + 64 + k] * s_g[288 + k];
        s_hs[tid] = v;
    }
    __syncthreads();

    // GEMM: relu(h2 @ W1[:, :64]^T + hs) . w2
    ulonglong2 h01 = *(const ulonglong2*)&s_hs[tx*4];
    ull acc[8] = {h01.x, h01.y, h01.x, h01.y, h01.x, h01.y, h01.x, h01.y};
    #pragma unroll 8
    for (int kk = 0; kk < 64; ++kk) {
        float a0 = s_X[(ty*4+0)*68 + kk];
        float a1 = s_X[(ty*4+1)*68 + kk];
        float a2 = s_X[(ty*4+2)*68 + kk];
        float a3 = s_X[(ty*4+3)*68 + kk];
        mk16(acc, a0, a1, a2, a3, &s_W[kk*68 + tx*4]);
    }
    float4 w2v = *(const float4*)&s_w2[tx*4];
    float b2v = b2[0];
    #pragma unroll
    for (int i = 0; i < 4; ++i) {
        float4 v = acc_f4(acc[2*i], acc[2*i+1]);
        float y = fmaxf(v.x, 0.f)*w2v.x + fmaxf(v.y, 0.f)*w2v.y
                + fmaxf(v.z, 0.f)*w2v.z + fmaxf(v.w, 0.f)*w2v.w;
        #pragma unroll
        for (int o = 8; o > 0; o >>= 1) y += __shfl_xor_sync(0xffffffffu, y, o);
        if (tx == 0) out[base + ty*4 + i] = y + b2v;
    }
}

// ---------------- launch --------------------------------------------------------
extern "C" void kernel_launch(void* const* d_in, const int* in_sizes, int n_in,
                              void* d_out, int out_size)
{
    const float* tf    = (const float*)d_in[0];
    const int*   types = (const int*)  d_in[1];
    const float* prev  = (const float*)d_in[2];
    const float* ew1   = (const float*)d_in[3];
    const float* eb1   = (const float*)d_in[4];
    const float* ew2   = (const float*)d_in[5];
    const float* eb2   = (const float*)d_in[6];
    const float* cont  = (const float*)d_in[7];
    const float* gw    = (const float*)d_in[8];
    const float* gb    = (const float*)d_in[9];
    const float* wih   = (const float*)d_in[10];
    const float* whh   = (const float*)d_in[11];
    const float* bih   = (const float*)d_in[12];
    const float* bhh   = (const float*)d_in[13];
    const float* hw1   = (const float*)d_in[14];
    const float* hb1   = (const float*)d_in[15];
    const float* hw2   = (const float*)d_in[16];
    const float* hb2   = (const float*)d_in[17];
    float* out = (float*)d_out;

    cudaFuncSetAttribute(k_layer, cudaFuncAttributeMaxDynamicSharedMemorySize, 69632);

    k_encbkt<<<1088, 256>>>(tf, types, ew1, eb1, ew2, eb2);
    for (int l = 0; l < 2; ++l) {
        k_gmat <<<dim3(Tt, Bb), 256>>>(l);
        k_layer<<<dim3(Tt, Bb), 256, 69632>>>(l, cont, gw, gb);
    }
    k_head<<<1024, 256>>>(prev, wih, whh, bih, bhh, hw1, hb1, hw2, hb2, out);
}

// round 6
// speedup vs baseline: 1.1576x; 1.0139x over previous
#include <cuda_runtime.h>
#include <math.h>

#define Bb 64
#define Nn 1024
#define Hh 64
#define Tt 10

// ---------------- scratch (device globals) ------------------------------------
__device__ __align__(16) float g_emb[Bb*Nn*Hh];
__device__ __align__(16) float g_h1 [Bb*Nn*Hh];
__device__ __align__(16) float g_h2 [Bb*Nn*Hh];
__device__ __align__(16) float g_G  [Bb*Tt*Hh*Hh];
__device__ __align__(16) float g_M  [Bb*Tt*Hh*Hh];
__device__ __align__(16) float g_inv[Bb*Nn];
__device__ int   g_idx[Bb*Tt*Nn];
__device__ int   g_cnt[Bb*Tt];
__device__ __align__(16) float g_ctx[Bb*Hh];

typedef unsigned long long ull;

#define FMA4(A, s, v) { (A).x += (s)*(v).x; (A).y += (s)*(v).y; (A).z += (s)*(v).z; (A).w += (s)*(v).w; }
#define FMA2(acc, a2, b2)  asm("fma.rn.f32x2 %0, %1, %2, %0;" : "+l"(acc) : "l"(a2), "l"(b2))
#define PACK_DUP(out, x)   asm("mov.b64 %0, {%1, %1};" : "=l"(out) : "r"(__float_as_uint(x)))
#define UNPACK2(lo, hi, p) asm("mov.b64 {%0, %1}, %2;" : "=r"(lo), "=r"(hi) : "l"(p))

__device__ __forceinline__ float4 acc_f4(ull p0, ull p1) {
    unsigned a, b, c, d;
    UNPACK2(a, b, p0); UNPACK2(c, d, p1);
    return make_float4(__uint_as_float(a), __uint_as_float(b),
                       __uint_as_float(c), __uint_as_float(d));
}

// 16 fp32 FMAs as 8 packed FFMA2: 4 row-scalars x one float4 of B
__device__ __forceinline__ void mk16(ull* acc, float a0, float a1, float a2, float a3,
                                     const float* bp) {
    ulonglong2 bv = *(const ulonglong2*)bp;
    ull ap;
    PACK_DUP(ap, a0); FMA2(acc[0], ap, bv.x); FMA2(acc[1], ap, bv.y);
    PACK_DUP(ap, a1); FMA2(acc[2], ap, bv.x); FMA2(acc[3], ap, bv.y);
    PACK_DUP(ap, a2); FMA2(acc[4], ap, bv.x); FMA2(acc[5], ap, bv.y);
    PACK_DUP(ap, a3); FMA2(acc[6], ap, bv.x); FMA2(acc[7], ap, bv.y);
}

// ---------------- K1: encoder (blocks 0..1023) + bucket (1024..1087) -----------
__global__ __launch_bounds__(256) void k_encbkt(
    const float* __restrict__ tf, const int* __restrict__ types,
    const float* __restrict__ w1, const float* __restrict__ b1,
    const float* __restrict__ w2, const float* __restrict__ b2)
{
    __shared__ __align__(16) float s_h1 [64*68];
    __shared__ __align__(16) float s_w2t[64*68];
    __shared__ __align__(16) float s_f[192];
    __shared__ __align__(16) float s_w1[192];
    __shared__ __align__(16) float s_b1[64];
    __shared__ __align__(16) float s_b2[64];
    __shared__ int s_cnt[16];
    int tid = threadIdx.x;

    if (blockIdx.x >= 1024) {               // ---- bucket path ----
        int b = blockIdx.x - 1024;
        if (tid < Tt) s_cnt[tid] = 0;
        if (tid < 64) g_ctx[b*64 + tid] = 0.f;
        __syncthreads();
        #pragma unroll
        for (int it = 0; it < 4; ++it) {
            int n = it*256 + tid;
            int t = types[b*Nn + n];
            int pos = atomicAdd(&s_cnt[t], 1);
            g_idx[(b*Tt + t)*Nn + pos] = n;
        }
        __syncthreads();
        if (tid < Tt) g_cnt[b*Tt + tid] = s_cnt[tid];
        return;
    }

    int tx = tid & 15, ty = tid >> 4;
    int base = blockIdx.x * 64;

    #pragma unroll
    for (int it = 0; it < 16; ++it) {
        int e = tid + it*256;
        int j = e >> 6, k = e & 63;
        s_w2t[k*68 + j] = w2[e];
    }
    if (tid < 192) { s_f[tid] = tf[base*3 + tid]; s_w1[tid] = w1[tid]; }
    if (tid < 64)  { s_b1[tid] = b1[tid]; s_b2[tid] = b2[tid]; }
    __syncthreads();

    #pragma unroll
    for (int it = 0; it < 16; ++it) {
        int e = tid + it*256;
        int row = e >> 6, k = e & 63;
        float h = s_f[row*3+0]*s_w1[k*3+0] + s_f[row*3+1]*s_w1[k*3+1]
                + s_f[row*3+2]*s_w1[k*3+2] + s_b1[k];
        s_h1[row*68 + k] = fmaxf(h, 0.f);
    }
    __syncthreads();

    ull acc[8] = {0,0,0,0,0,0,0,0};
    #pragma unroll 8
    for (int kk = 0; kk < 64; ++kk) {
        float a0 = s_h1[(ty*4+0)*68 + kk];
        float a1 = s_h1[(ty*4+1)*68 + kk];
        float a2 = s_h1[(ty*4+2)*68 + kk];
        float a3 = s_h1[(ty*4+3)*68 + kk];
        mk16(acc, a0, a1, a2, a3, &s_w2t[kk*68 + tx*4]);
    }
    float4 bias = *(const float4*)&s_b2[tx*4];
    #pragma unroll
    for (int i = 0; i < 4; ++i) {
        float4 v = acc_f4(acc[2*i], acc[2*i+1]);
        v.x += bias.x; v.y += bias.y; v.z += bias.z; v.w += bias.w;
        float sq = v.x*v.x + v.y*v.y + v.z*v.z + v.w*v.w;
        #pragma unroll
        for (int o = 8; o > 0; o >>= 1) sq += __shfl_xor_sync(0xffffffffu, sq, o);
        float inv = 1.f / fmaxf(sqrtf(sq), 1e-12f);
        int r = base + ty*4 + i;
        *(float4*)&g_emb[r*64 + tx*4] = v;
        if (tx == 0) g_inv[r] = inv;
    }
}

// ---------------- K2: G_t = Nrm^T @ H per (t,b) --------------------------------
__global__ __launch_bounds__(256) void k_gmat(int layer)
{
    const float4* emb4 = (const float4*)g_emb;
    const float4* h4   = (const float4*)((layer == 0) ? g_emb : g_h1);
    __shared__ __align__(16) float s_A [64*68];
    __shared__ __align__(16) float s_Bh[64*68];
    int t = blockIdx.x, b = blockIdx.y;
    int tid = threadIdx.x;
    int tx = tid & 15, ty = tid >> 4;
    int Kt = g_cnt[b*Tt + t];
    const int* lst = &g_idx[(b*Tt + t)*Nn];
    ull acc[8] = {0,0,0,0,0,0,0,0};

    for (int r0 = 0; r0 < Kt; r0 += 64) {
        #pragma unroll
        for (int it = 0; it < 4; ++it) {
            int e = tid + it*256;
            int rr = e >> 4, kq = e & 15;
            int r = r0 + rr;
            float4 v = make_float4(0.f,0.f,0.f,0.f);
            float4 w = v;
            if (r < Kt) {
                int row = __ldg(&lst[r]);
                float iv = __ldg(&g_inv[(b<<10) + row]);
                int gi = ((b<<10) + row)*16 + kq;
                v = emb4[gi];
                w = (layer == 0) ? v : h4[gi];
                v.x *= iv; v.y *= iv; v.z *= iv; v.w *= iv;
            }
            *(float4*)&s_Bh[rr*68 + kq*4] = w;
            *(float4*)&s_A [rr*68 + kq*4] = v;
        }
        __syncthreads();
        #pragma unroll 8
        for (int rr = 0; rr < 64; ++rr) {
            float4 a = *(const float4*)&s_A[rr*68 + ty*4];
            mk16(acc, a.x, a.y, a.z, a.w, &s_Bh[rr*68 + tx*4]);
        }
        __syncthreads();
    }
    float* Gp = &g_G[(b*Tt + t)*4096];
    #pragma unroll
    for (int i = 0; i < 4; ++i)
        *(float4*)&Gp[(ty*4 + i)*64 + tx*4] = acc_f4(acc[2*i], acc[2*i+1]);
}

// ---------------- K2b: M[b,tp] = sum_t sigmoid(C[tp,t]) G[b,t] -----------------
// grid (64,8), 128 threads: each thread one float4 lane, all t in regs
__global__ __launch_bounds__(128) void k_combine(const float* __restrict__ cont)
{
    __shared__ float s_S[Tt*Tt];
    int b = blockIdx.x, tid = threadIdx.x;
    if (tid < Tt*Tt) s_S[tid] = 1.f / (1.f + expf(-cont[tid]));
    __syncthreads();
    int i4 = blockIdx.y * 128 + tid;       // 0..1023 float4 within 64x64
    const float4* G4 = (const float4*)g_G + (size_t)b*10240;
    float4*       M4 = (float4*)g_M       + (size_t)b*10240;
    float4 g[Tt];
    #pragma unroll
    for (int t = 0; t < Tt; ++t) g[t] = G4[t*1024 + i4];
    #pragma unroll
    for (int tp = 0; tp < Tt; ++tp) {
        float4 o = make_float4(0.f,0.f,0.f,0.f);
        #pragma unroll
        for (int t = 0; t < Tt; ++t) {
            float s = s_S[tp*Tt + t];
            FMA4(o, s, g[t]);
        }
        M4[tp*1024 + i4] = o;
    }
}

// ---------------- K3: Agg = Nrm @ M ; Hout = relu((H+Agg)@W^T+b) ---------------
// grid (10,64), 256 threads, dyn smem 69632
__global__ __launch_bounds__(256) void k_layer(
    int layer, const float* __restrict__ gnn_w, const float* __restrict__ gnn_b)
{
    const float* hin  = (layer == 0) ? g_emb : g_h1;
    float*       hout = (layer == 0) ? g_h1  : g_h2;
    const float4* emb4 = (const float4*)g_emb;
    extern __shared__ __align__(16) float sm[];
    float* SA = sm;            // M   [k][d] stride 68
    float* SW = sm + 4352;     // W^T [k][c] stride 68
    float* SB = sm + 8704;     // gathered nrm [r][k] stride 68
    float* SC = sm + 13056;    // X   [r][k] stride 68
    __shared__ __align__(16) float s_bias[64];
    __shared__ __align__(16) float s_csum[16][64];

    int t = blockIdx.x, b = blockIdx.y;
    int tid = threadIdx.x;
    int tx = tid & 15, ty = tid >> 4;
    int Kt = g_cnt[b*Tt + t];
    if (Kt == 0) return;

    const float* Wp = gnn_w + layer*4096;
    if (tid < 64) s_bias[tid] = gnn_b[layer*64 + tid];
    #pragma unroll
    for (int it = 0; it < 16; ++it) {
        int e = tid + it*256;
        SW[(e & 63)*68 + (e >> 6)] = Wp[e];     // transpose -> [k][c]
    }
    const float4* Mp4 = (const float4*)&g_M[(b*Tt + t)*4096];
    #pragma unroll
    for (int it = 0; it < 4; ++it) {
        int e = tid + it*256;
        *(float4*)&SA[(e >> 4)*68 + (e & 15)*4] = Mp4[e];
    }

    const int* lst = &g_idx[(b*Tt + t)*Nn];
    float4 psum = make_float4(0.f,0.f,0.f,0.f);
    __syncthreads();

    for (int r0 = 0; r0 < Kt; r0 += 64) {
        #pragma unroll
        for (int it = 0; it < 4; ++it) {
            int e = tid + it*256;
            int rr = e >> 4, kq = e & 15;
            int r = r0 + rr;
            float4 v = make_float4(0.f,0.f,0.f,0.f);
            if (r < Kt) {
                int row = __ldg(&lst[r]);
                float iv = __ldg(&g_inv[(b<<10) + row]);
                v = emb4[((b<<10) + row)*16 + kq];
                v.x *= iv; v.y *= iv; v.z *= iv; v.w *= iv;
            }
            *(float4*)&SB[rr*68 + kq*4] = v;
        }
        __syncthreads();

        // GEMM1: Agg = nrm @ M
        ull acc[8] = {0,0,0,0,0,0,0,0};
        #pragma unroll 8
        for (int kk = 0; kk < 64; ++kk) {
            float a0 = SB[(ty*4+0)*68 + kk];
            float a1 = SB[(ty*4+1)*68 + kk];
            float a2 = SB[(ty*4+2)*68 + kk];
            float a3 = SB[(ty*4+3)*68 + kk];
            mk16(acc, a0, a1, a2, a3, &SA[kk*68 + tx*4]);
        }
        #pragma unroll
        for (int i = 0; i < 4; ++i) {
            int r = r0 + ty*4 + i;
            float4 x = acc_f4(acc[2*i], acc[2*i+1]);
            if (r < Kt) {
                int row = __ldg(&lst[r]);
                float4 hv = *(const float4*)&hin[((b<<10) + row)*64 + tx*4];
                x.x += hv.x; x.y += hv.y; x.z += hv.z; x.w += hv.w;
            } else {
                x = make_float4(0.f,0.f,0.f,0.f);
            }
            *(float4*)&SC[(ty*4+i)*68 + tx*4] = x;
        }
        __syncthreads();

        // GEMM2: Out = X @ W^T
        ull acc2[8] = {0,0,0,0,0,0,0,0};
        #pragma unroll 8
        for (int kk = 0; kk < 64; ++kk) {
            float a0 = SC[(ty*4+0)*68 + kk];
            float a1 = SC[(ty*4+1)*68 + kk];
            float a2 = SC[(ty*4+2)*68 + kk];
            float a3 = SC[(ty*4+3)*68 + kk];
            mk16(acc2, a0, a1, a2, a3, &SW[kk*68 + tx*4]);
        }
        float4 bias = *(const float4*)&s_bias[tx*4];
        #pragma unroll
        for (int i = 0; i < 4; ++i) {
            int r = r0 + ty*4 + i;
            if (r < Kt) {
                int row = __ldg(&lst[r]);
                float4 o = acc_f4(acc2[2*i], acc2[2*i+1]);
                o.x = fmaxf(o.x + bias.x, 0.f);
                o.y = fmaxf(o.y + bias.y, 0.f);
                o.z = fmaxf(o.z + bias.z, 0.f);
                o.w = fmaxf(o.w + bias.w, 0.f);
                *(float4*)&hout[((b<<10) + row)*64 + tx*4] = o;
                if (layer == 1) { psum.x += o.x; psum.y += o.y; psum.z += o.z; psum.w += o.w; }
            }
        }
        __syncthreads();
    }

    if (layer == 1) {
        *(float4*)&s_csum[ty][tx*4] = psum;
        __syncthreads();
        if (tid < 64) {
            float s = 0.f;
            #pragma unroll
            for (int q = 0; q < 16; ++q) s += s_csum[q][tid];
            atomicAdd(&g_ctx[b*64 + tid], s);
        }
    }
}

// ---------------- K4: head (+GRU computed per-block, K reduced to 64) ----------
__global__ __launch_bounds__(256) void k_head(
    const float* __restrict__ prev, const float* __restrict__ wih,
    const float* __restrict__ whh,  const float* __restrict__ bih,
    const float* __restrict__ bhh,
    const float* __restrict__ w1, const float* __restrict__ b1,
    const float* __restrict__ w2, const float* __restrict__ b2,
    float* __restrict__ out)
{
    __shared__ __align__(16) float s_X[64*68];
    __shared__ __align__(16) float s_W[64*68];
    __shared__ __align__(16) float s_g[320];   // ctx|prev|gi|gh|ns
    __shared__ __align__(16) float s_hs[64];
    __shared__ __align__(16) float s_w2[64];
    int tid = threadIdx.x;
    int tx = tid & 15, ty = tid >> 4;
    int u = blockIdx.x;
    int base = u << 6;
    int b = u >> 4;

    if (tid < 64)  s_g[tid] = g_ctx[b*64 + tid] * (1.f/1024.f);
    else if (tid < 96) s_g[tid] = prev[b*32 + (tid - 64)];
    #pragma unroll
    for (int it = 0; it < 16; ++it) {
        int e = tid + it*256;
        int j = e >> 6, k = e & 63;
        s_W[k*68 + j] = w1[j*96 + k];           // W1[:, :64] transposed
    }
    if (tid < 64) s_w2[tid] = w2[tid];
    const float4* h24 = (const float4*)g_h2;
    #pragma unroll
    for (int it = 0; it < 4; ++it) {
        int e = tid + it*256;
        int rr = e >> 4, kq = e & 15;
        *(float4*)&s_X[rr*68 + kq*4] = h24[(base + rr)*16 + kq];
    }
    __syncthreads();

    if (tid < 96) {
        float gi = bih[tid], gh = bhh[tid];
        #pragma unroll 16
        for (int k = 0; k < 64; ++k) gi += s_g[k] * wih[tid*64 + k];
        #pragma unroll 16
        for (int k = 0; k < 32; ++k) gh += s_g[64 + k] * whh[tid*32 + k];
        s_g[96 + tid] = gi; s_g[192 + tid] = gh;
    }
    __syncthreads();
    if (tid < 32) {
        float r  = 1.f / (1.f + expf(-(s_g[96  + tid] + s_g[192 + tid])));
        float z  = 1.f / (1.f + expf(-(s_g[128 + tid] + s_g[224 + tid])));
        float nn = tanhf(s_g[160 + tid] + r * s_g[256 + tid]);
        float ns = (1.f - z)*nn + z*s_g[64 + tid];
        s_g[288 + tid] = ns;
        if ((u & 15) == 0) out[Bb*Nn + b*32 + tid] = ns;
    }
    __syncthreads();
    if (tid < 64) {
        float v = b1[tid];
        #pragma unroll
        for (int k = 0; k < 32; ++k) v += w1[tid*96 + 64 + k] * s_g[288 + k];
        s_hs[tid] = v;
    }
    __syncthreads();

    ulonglong2 h01 = *(const ulonglong2*)&s_hs[tx*4];
    ull acc[8] = {h01.x, h01.y, h01.x, h01.y, h01.x, h01.y, h01.x, h01.y};
    #pragma unroll 8
    for (int kk = 0; kk < 64; ++kk) {
        float a0 = s_X[(ty*4+0)*68 + kk];
        float a1 = s_X[(ty*4+1)*68 + kk];
        float a2 = s_X[(ty*4+2)*68 + kk];
        float a3 = s_X[(ty*4+3)*68 + kk];
        mk16(acc, a0, a1, a2, a3, &s_W[kk*68 + tx*4]);
    }
    float4 w2v = *(const float4*)&s_w2[tx*4];
    float b2v = b2[0];
    #pragma unroll
    for (int i = 0; i < 4; ++i) {
        float4 v = acc_f4(acc[2*i], acc[2*i+1]);
        float y = fmaxf(v.x, 0.f)*w2v.x + fmaxf(v.y, 0.f)*w2v.y
                + fmaxf(v.z, 0.f)*w2v.z + fmaxf(v.w, 0.f)*w2v.w;
        #pragma unroll
        for (int o = 8; o > 0; o >>= 1) y += __shfl_xor_sync(0xffffffffu, y, o);
        if (tx == 0) out[base + ty*4 + i] = y + b2v;
    }
}

// ---------------- launch --------------------------------------------------------
extern "C" void kernel_launch(void* const* d_in, const int* in_sizes, int n_in,
                              void* d_out, int out_size)
{
    const float* tf    = (const float*)d_in[0];
    const int*   types = (const int*)  d_in[1];
    const float* prev  = (const float*)d_in[2];
    const float* ew1   = (const float*)d_in[3];
    const float* eb1   = (const float*)d_in[4];
    const float* ew2   = (const float*)d_in[5];
    const float* eb2   = (const float*)d_in[6];
    const float* cont  = (const float*)d_in[7];
    const float* gw    = (const float*)d_in[8];
    const float* gb    = (const float*)d_in[9];
    const float* wih   = (const float*)d_in[10];
    const float* whh   = (const float*)d_in[11];
    const float* bih   = (const float*)d_in[12];
    const float* bhh   = (const float*)d_in[13];
    const float* hw1   = (const float*)d_in[14];
    const float* hb1   = (const float*)d_in[15];
    const float* hw2   = (const float*)d_in[16];
    const float* hb2   = (const float*)d_in[17];
    float* out = (float*)d_out;

    cudaFuncSetAttribute(k_layer, cudaFuncAttributeMaxDynamicSharedMemorySize, 69632);

    k_encbkt<<<1088, 256>>>(tf, types, ew1, eb1, ew2, eb2);
    for (int l = 0; l < 2; ++l) {
        k_gmat   <<<dim3(Tt, Bb), 256>>>(l);
        k_combine<<<dim3(Bb, 8), 128>>>(cont);
        k_layer  <<<dim3(Tt, Bb), 256, 69632>>>(l, gw, gb);
    }
    k_head<<<1024, 256>>>(prev, wih, whh, bih, bhh, hw1, hb1, hw2, hb2, out);
}